// round 13
// baseline (speedup 1.0000x reference)
#include <cuda_runtime.h>

// ---------------------------------------------------------------------------
// Fully fused MSE + SSIM loss, 32x1x512x512 fp32 -> scalar. ONE kernel.
// Round-13: R7's interleaved-smem staging (LDS.128 delivers ALIGNED (p,t)
// register pairs -> zero pairing MOVs for fma.rn.f32x2, the ALU thief at
// 35% in gmem-direct R8) combined with R8's 5-CTA occupancy: TOR=40 keeps
// s2+hb at 44KB. 3 phases/tile: float4 load+pack+MSE -> hconv from s2 ->
// vconv from permuted hb. Packed fma.rn.f32x2 throughout.
// ---------------------------------------------------------------------------

#define H 512
#define W 512
#define B 32
#define OV 502            // valid output size (512 - 11 + 1)
#define TOR 40            // output tile rows
#define TOC 32            // output tile cols
#define TIR 50            // input tile rows (TOR + 10)
#define S2S 44            // s2 row stride in u64 (352B)
#define HBS 33            // hb row stride in ulonglong2 (528B: coeff 4 mod 32)
#define NTROW 13          // row tiles (13*40 = 520 >= 502)
#define NBLOCKS (16 * NTROW * 32)   // 6656

#define S2_BYTES (TIR * S2S * 8)           // 17600
#define HB_OFF   S2_BYTES
#define WS_OFF   (HB_OFF + TIR * HBS * 16) // 44000
#define SMEM_SZ  (WS_OFF + 64)             // 44064 -> 5 CTAs/SM

typedef unsigned long long u64;

__device__ __forceinline__ u64 pk2(float lo, float hi) {
    u64 r; asm("mov.b64 %0, {%1, %2};" : "=l"(r) : "f"(lo), "f"(hi)); return r;
}
__device__ __forceinline__ void upk2(u64 v, float& lo, float& hi) {
    asm("mov.b64 {%0, %1}, %2;" : "=f"(lo), "=f"(hi) : "l"(v));
}
__device__ __forceinline__ u64 ffma2(u64 a, u64 w, u64 c) {
    u64 d; asm("fma.rn.f32x2 %0, %1, %2, %3;" : "=l"(d) : "l"(a), "l"(w), "l"(c));
    return d;
}

// 11-tap Gaussian, sigma=1.5, normalized; symmetric -> 6 distinct values.
#define GW0 0.00102838f
#define GW1 0.00759875f
#define GW2 0.03600077f
#define GW3 0.10936080f
#define GW4 0.21300549f
#define GW5 0.26601166f
#define DECLARE_W2                                                            \
    const u64 W2[11] = {                                                      \
        pk2(GW0, GW0), pk2(GW1, GW1), pk2(GW2, GW2), pk2(GW3, GW3),           \
        pk2(GW4, GW4), pk2(GW5, GW5),                                         \
        pk2(GW4, GW4), pk2(GW3, GW3), pk2(GW2, GW2), pk2(GW1, GW1),           \
        pk2(GW0, GW0) };

__device__ double g_accum[2] = {0.0, 0.0};   // [0]=mse sum, [1]=ssim sum
__device__ unsigned int g_count = 0;

__global__ __launch_bounds__(256, 5) void fused_kernel(
    const float* __restrict__ pred, const float* __restrict__ targ,
    float* __restrict__ out)
{
    extern __shared__ __align__(16) char dsm[];
    u64 (*s2)[S2S] = (u64(*)[S2S])dsm;                       // (p,t) pairs
    ulonglong2 (*hb)[HBS] = (ulonglong2(*)[HBS])(dsm + HB_OFF);
    float* ws = (float*)(dsm + WS_OFF);

    const int tid = threadIdx.x;
    const int r0 = blockIdx.y * TOR;
    const int c0 = blockIdx.x * TOC;
    const float* pim = pred + (size_t)blockIdx.z * (H * W);
    const float* tim = targ + (size_t)blockIdx.z * (H * W);

    float msum = 0.0f, lsum = 0.0f;

    // ---- phase 1: load 50x44 halo as float4 pairs, pack interleaved (p,t)
    // into s2, fuse MSE over owned pixels. 550 chunks of 4 px.
    // Ownership: row < TOR, chunk < 8, r0+row < H (clamp dups excluded).
    for (int i = tid; i < TIR * 11; i += 256) {
        int row = i / 11, q = i - row * 11;
        int gr = min(r0 + row, H - 1);
        int gc = min(c0 + 4 * q, W - 4);
        const float4 P = *(const float4*)(pim + gr * W + gc);
        const float4 T = *(const float4*)(tim + gr * W + gc);
        if (row < TOR && q < 8 && (r0 + row) < H) {
            float d0 = P.x - T.x, d1 = P.y - T.y;
            float d2 = P.z - T.z, d3 = P.w - T.w;
            msum = fmaf(d0, d0, msum); msum = fmaf(d1, d1, msum);
            msum = fmaf(d2, d2, msum); msum = fmaf(d3, d3, msum);
        }
        *(ulonglong2*)&s2[row][4 * q + 0] =
            make_ulonglong2(pk2(P.x, T.x), pk2(P.y, T.y));
        *(ulonglong2*)&s2[row][4 * q + 2] =
            make_ulonglong2(pk2(P.z, T.z), pk2(P.w, T.w));
    }
    __syncthreads();

    // ---- phase 2: hconv from s2 (LDS.128 -> aligned (p,t) pairs, no MOVs).
    // Row-major tasks: 50 rows x 8 cgs; quarter-warp = 8 cgs of one row
    // -> contiguous 128B LDS phases, conflict-free. Permuted STS to hb.
    {
        DECLARE_W2
        for (int t = tid; t < TIR * 8; t += 256) {
            int row = t >> 3, cg = t & 7;

            u64 win[14];
            #pragma unroll
            for (int q = 0; q < 7; q++) {
                ulonglong2 v = *(const ulonglong2*)&s2[row][4 * cg + 2 * q];
                win[2 * q + 0] = v.x;
                win[2 * q + 1] = v.y;
            }

            u64 a0 = 0, a1 = 0, a2 = 0, a3 = 0;
            #pragma unroll
            for (int k = 0; k < 11; k++) {
                a0 = ffma2(win[k + 0], W2[k], a0);
                a1 = ffma2(win[k + 1], W2[k], a1);
                a2 = ffma2(win[k + 2], W2[k], a2);
                a3 = ffma2(win[k + 3], W2[k], a3);
            }
            // (p,t) -> (p^2+t^2, p*t): operands are halves of the pair
            // (free reads); result pair allocated directly (free pack).
            #pragma unroll
            for (int k = 0; k < 14; k++) {
                float p, tt;
                upk2(win[k], p, tt);
                win[k] = pk2(fmaf(p, p, tt * tt), p * tt);
            }
            u64 b0 = 0, b1 = 0, b2 = 0, b3 = 0;
            #pragma unroll
            for (int k = 0; k < 11; k++) {
                b0 = ffma2(win[k + 0], W2[k], b0);
                b1 = ffma2(win[k + 1], W2[k], b1);
                b2 = ffma2(win[k + 2], W2[k], b2);
                b3 = ffma2(win[k + 3], W2[k], b3);
            }
            // permuted store: storage col = cg + 8j holds actual col 4cg+j.
            // Quarter-warp writes 128B contiguous -> 4-wavefront STS.128.
            hb[row][cg +  0] = make_ulonglong2(a0, b0);
            hb[row][cg +  8] = make_ulonglong2(a1, b1);
            hb[row][cg + 16] = make_ulonglong2(a2, b2);
            hb[row][cg + 24] = make_ulonglong2(a3, b3);
        }
    }
    __syncthreads();

    // ---- phase 3: vconv streaming: thread owns (storage col, 5 rows).
    // 15 LDS.128, 20 packed accumulators, SSIM epilogue.
    {
        DECLARE_W2
        const int c = tid & 31;                    // storage column
        const int acol = 4 * (c & 7) + (c >> 3);   // actual column
        const int rb = (tid >> 5) * 5;             // 0,5,...,35

        u64 accA[5], accB[5];
        #pragma unroll
        for (int j = 0; j < 5; j++) { accA[j] = 0; accB[j] = 0; }

        #pragma unroll
        for (int k = 0; k < 15; k++) {
            ulonglong2 v = hb[rb + k][c];
            #pragma unroll
            for (int j = 0; j < 5; j++) {
                if (k - j >= 0 && k - j <= 10) {
                    accA[j] = ffma2(v.x, W2[k - j], accA[j]);
                    accB[j] = ffma2(v.y, W2[k - j], accB[j]);
                }
            }
        }

        const float C1 = 1e-4f, C2 = 9e-4f;
        const int ocol = c0 + acol;
        #pragma unroll
        for (int j = 0; j < 5; j++) {
            int orow = r0 + rb + j;
            if (orow < OV && ocol < OV) {
                float m1, m2, bsv, bptv;
                upk2(accA[j], m1, m2);
                upk2(accB[j], bsv, bptv);
                float m1s = m1 * m1, m2s = m2 * m2, m12 = m1 * m2;
                float musum = m1s + m2s;
                float sigsum = bsv - musum;           // sigma1^2 + sigma2^2
                float s12 = bptv - m12;               // sigma12
                float num = (2.0f * m12 + C1) * (2.0f * s12 + C2);
                float den = (musum + C1) * (sigsum + C2) + 1e-6f;
                lsum += __fdividef(num, den);
            }
        }
    }

    // ---- block reduction of (msum, lsum)
    #pragma unroll
    for (int o = 16; o; o >>= 1) {
        msum += __shfl_down_sync(0xffffffffu, msum, o);
        lsum += __shfl_down_sync(0xffffffffu, lsum, o);
    }
    int lane = tid & 31, wid = tid >> 5;
    if (!lane) { ws[wid] = msum; ws[8 + wid] = lsum; }
    __syncthreads();
    if (wid == 0) {
        msum = (lane < 8) ? ws[lane] : 0.0f;
        lsum = (lane < 8) ? ws[8 + lane] : 0.0f;
        #pragma unroll
        for (int o = 4; o; o >>= 1) {
            msum += __shfl_down_sync(0xffffffffu, msum, o);
            lsum += __shfl_down_sync(0xffffffffu, lsum, o);
        }
        if (!lane) {
            atomicAdd(&g_accum[0], (double)msum);
            atomicAdd(&g_accum[1], (double)lsum);
            __threadfence();
            unsigned done = atomicAdd(&g_count, 1u);
            if (done == NBLOCKS - 1) {
                // all blocks' fenced atomics visible; read via atomic RMW
                double a0 = atomicAdd(&g_accum[0], 0.0);
                double a1 = atomicAdd(&g_accum[1], 0.0);
                double mse = a0 / (double)(B * H * W);
                double smean = a1 / ((double)B * OV * OV);
                out[0] = (float)(0.6 * mse + 0.4 * (1.0 - smean));
                // reset for next graph replay (replays are serialized)
                g_accum[0] = 0.0;
                g_accum[1] = 0.0;
                g_count = 0u;
            }
        }
    }
}

// ---------------------------------------------------------------------------
extern "C" void kernel_launch(void* const* d_in, const int* in_sizes, int n_in,
                              void* d_out, int out_size)
{
    const float* pred = (const float*)d_in[0];
    const float* targ = (const float*)d_in[1];

    cudaFuncSetAttribute(fused_kernel,
                         cudaFuncAttributeMaxDynamicSharedMemorySize, SMEM_SZ);

    dim3 grid(16, NTROW, B);   // 16 col-tiles x 13 row-tiles x 32 images
    fused_kernel<<<grid, 256, SMEM_SZ>>>(pred, targ, (float*)d_out);
}

// round 14
// speedup vs baseline: 1.1308x; 1.1308x over previous
#include <cuda_runtime.h>

// ---------------------------------------------------------------------------
// Fully fused MSE + SSIM loss, 32x1x512x512 fp32 -> scalar. ONE kernel.
// Round-14: the round-8 body (best measured: 51.0us) with instruction-
// subtractive micro-opts only:
//  - template<bool INTERIOR>: non-border tiles (~85%) drop every row/col
//    clamp (IMNMX) in hconv and all bounds checks in the vconv epilogue.
//  - __fdividef in the SSIM epilogue.
// Dataflow identical to R8: gmem-direct hconv (coalesced float4), permuted
// conflict-free STS (storage col = cg + 8j), packed fma.rn.f32x2 chains,
// fused MSE, per-block reduce + atomic pair, last-block epilogue.
// ---------------------------------------------------------------------------

#define H 512
#define W 512
#define B 32
#define OV 502            // valid output size (512 - 11 + 1)
#define TOR 48            // output tile rows
#define TOC 32            // output tile cols
#define TIR 58            // input tile rows  (TOR + 10)
#define HBS 33            // hb row stride in ulonglong2 (528B: coeff 4 mod 32)
#define NTROW 11          // row tiles (11*48 = 528 >= 502)
#define NBLOCKS (16 * NTROW * 32)

#define HB_BYTES  (TIR * HBS * 16)       // 30624
#define SMEM_SZ   (HB_BYTES + 64)        // 30688

typedef unsigned long long u64;

__device__ __forceinline__ u64 pk2(float lo, float hi) {
    u64 r; asm("mov.b64 %0, {%1, %2};" : "=l"(r) : "f"(lo), "f"(hi)); return r;
}
__device__ __forceinline__ void upk2(u64 v, float& lo, float& hi) {
    asm("mov.b64 {%0, %1}, %2;" : "=f"(lo), "=f"(hi) : "l"(v));
}
__device__ __forceinline__ u64 ffma2(u64 a, u64 w, u64 c) {
    u64 d; asm("fma.rn.f32x2 %0, %1, %2, %3;" : "=l"(d) : "l"(a), "l"(w), "l"(c));
    return d;
}

// 11-tap Gaussian, sigma=1.5, normalized; symmetric -> 6 distinct values.
#define GW0 0.00102838f
#define GW1 0.00759875f
#define GW2 0.03600077f
#define GW3 0.10936080f
#define GW4 0.21300549f
#define GW5 0.26601166f
#define DECLARE_W2                                                            \
    const u64 W2[11] = {                                                      \
        pk2(GW0, GW0), pk2(GW1, GW1), pk2(GW2, GW2), pk2(GW3, GW3),           \
        pk2(GW4, GW4), pk2(GW5, GW5),                                         \
        pk2(GW4, GW4), pk2(GW3, GW3), pk2(GW2, GW2), pk2(GW1, GW1),           \
        pk2(GW0, GW0) };

__device__ double g_accum[2] = {0.0, 0.0};   // [0]=mse sum, [1]=ssim sum
__device__ unsigned int g_count = 0;

// ---- per-tile compute, specialized on border handling --------------------
template <bool INTERIOR>
__device__ __forceinline__ void tile_compute(
    const float* __restrict__ pim, const float* __restrict__ tim,
    int r0, int c0, int tid, ulonglong2 (*hb)[HBS],
    float& msum, float& lsum)
{
    // ---- fused gmem-load + horizontal conv. Row-major tasks: 58 rows x
    // 8 col-groups; warp lanes = (cg, row) -> coalesced LDG, conflict-free
    // STS with the cg+8j column permutation.
    {
        DECLARE_W2
        for (int t = tid; t < TIR * 8; t += 256) {
            int row = t >> 3, cg = t & 7;
            int gr = INTERIOR ? (r0 + row) : min(r0 + row, H - 1);
            const float* prow = pim + gr * W;
            const float* trow = tim + gr * W;
            const int cbase = c0 + 4 * cg;

            float4 P[4], T[4];
            #pragma unroll
            for (int j = 0; j < 4; j++) {
                int gc = INTERIOR ? (cbase + 4 * j)
                                  : min(cbase + 4 * j, W - 4);
                P[j] = *(const float4*)(prow + gc);
                T[j] = *(const float4*)(trow + gc);
            }

            // MSE: this task owns pixels (gr, cbase..cbase+3) exactly once
            // (clamped bottom rows excluded via r0+row < H on borders).
            bool own = INTERIOR ? (row < TOR)
                                : (row < TOR && (r0 + row) < H);
            if (own) {
                float d0 = P[0].x - T[0].x, d1 = P[0].y - T[0].y;
                float d2 = P[0].z - T[0].z, d3 = P[0].w - T[0].w;
                msum = fmaf(d0, d0, msum); msum = fmaf(d1, d1, msum);
                msum = fmaf(d2, d2, msum); msum = fmaf(d3, d3, msum);
            }

            u64 win[14];
            #pragma unroll
            for (int j = 0; j < 4; j++) {
                if (4 * j + 0 < 14) win[4 * j + 0] = pk2(P[j].x, T[j].x);
                if (4 * j + 1 < 14) win[4 * j + 1] = pk2(P[j].y, T[j].y);
                if (4 * j + 2 < 14) win[4 * j + 2] = pk2(P[j].z, T[j].z);
                if (4 * j + 3 < 14) win[4 * j + 3] = pk2(P[j].w, T[j].w);
            }

            u64 a0 = 0, a1 = 0, a2 = 0, a3 = 0;
            #pragma unroll
            for (int k = 0; k < 11; k++) {
                a0 = ffma2(win[k + 0], W2[k], a0);
                a1 = ffma2(win[k + 1], W2[k], a1);
                a2 = ffma2(win[k + 2], W2[k], a2);
                a3 = ffma2(win[k + 3], W2[k], a3);
            }
            #pragma unroll
            for (int k = 0; k < 14; k++) {   // (p,t) -> (p^2+t^2, p*t)
                float p, tt;
                upk2(win[k], p, tt);
                win[k] = pk2(fmaf(p, p, tt * tt), p * tt);
            }
            u64 b0 = 0, b1 = 0, b2 = 0, b3 = 0;
            #pragma unroll
            for (int k = 0; k < 11; k++) {
                b0 = ffma2(win[k + 0], W2[k], b0);
                b1 = ffma2(win[k + 1], W2[k], b1);
                b2 = ffma2(win[k + 2], W2[k], b2);
                b3 = ffma2(win[k + 3], W2[k], b3);
            }
            // permuted store: storage col = cg + 8j holds actual col 4cg+j.
            // Quarter-warp (8 lanes, same row, cg 0..7) writes 128B
            // contiguous -> 4-wavefront STS.128.
            hb[row][cg +  0] = make_ulonglong2(a0, b0);
            hb[row][cg +  8] = make_ulonglong2(a1, b1);
            hb[row][cg + 16] = make_ulonglong2(a2, b2);
            hb[row][cg + 24] = make_ulonglong2(a3, b3);
        }
    }
    __syncthreads();

    // ---- vertical 11-tap conv, streaming: each thread owns (storage col,
    // 6 rows). 16 LDS.128, 24 packed accumulators, then SSIM epilogue.
    {
        DECLARE_W2
        const int c = tid & 31;                    // storage column
        const int acol = 4 * (c & 7) + (c >> 3);   // actual column
        const int rb = (tid >> 5) * 6;             // 0,6,...,42

        u64 accA[6], accB[6];
        #pragma unroll
        for (int j = 0; j < 6; j++) { accA[j] = 0; accB[j] = 0; }

        #pragma unroll
        for (int k = 0; k < 16; k++) {
            ulonglong2 v = hb[rb + k][c];
            #pragma unroll
            for (int j = 0; j < 6; j++) {
                if (k - j >= 0 && k - j <= 10) {
                    accA[j] = ffma2(v.x, W2[k - j], accA[j]);
                    accB[j] = ffma2(v.y, W2[k - j], accB[j]);
                }
            }
        }

        const float C1 = 1e-4f, C2 = 9e-4f;
        const int ocol = c0 + acol;
        #pragma unroll
        for (int j = 0; j < 6; j++) {
            int orow = r0 + rb + j;
            // interior tiles: r0 <= 432, c0 <= 448 -> orow <= 479 < OV and
            // ocol <= 479 < OV always; drop the predicate entirely.
            bool valid = INTERIOR ? true : (orow < OV && ocol < OV);
            if (valid) {
                float m1, m2, bsv, bptv;
                upk2(accA[j], m1, m2);
                upk2(accB[j], bsv, bptv);
                float m1s = m1 * m1, m2s = m2 * m2, m12 = m1 * m2;
                float musum = m1s + m2s;
                float sigsum = bsv - musum;           // sigma1^2 + sigma2^2
                float s12 = bptv - m12;               // sigma12
                float num = (2.0f * m12 + C1) * (2.0f * s12 + C2);
                float den = (musum + C1) * (sigsum + C2) + 1e-6f;
                lsum += __fdividef(num, den);
            }
        }
    }
}

__global__ __launch_bounds__(256, 5) void fused_kernel(
    const float* __restrict__ pred, const float* __restrict__ targ,
    float* __restrict__ out)
{
    extern __shared__ __align__(16) char dsm[];
    ulonglong2 (*hb)[HBS] = (ulonglong2(*)[HBS])dsm;   // (A,B) packed pairs
    float* ws = (float*)(dsm + HB_BYTES);

    const int tid = threadIdx.x;
    const int r0 = blockIdx.y * TOR;
    const int c0 = blockIdx.x * TOC;
    const float* pim = pred + (size_t)blockIdx.z * (H * W);
    const float* tim = targ + (size_t)blockIdx.z * (H * W);

    float msum = 0.0f, lsum = 0.0f;

    // interior iff no row clamp (r0+57 <= 511), no col clamp
    // (c0+28+12 <= 508), and all outputs valid (guaranteed by the same).
    if (r0 + TIR <= H && c0 + 40 <= W - 4)
        tile_compute<true >(pim, tim, r0, c0, tid, hb, msum, lsum);
    else
        tile_compute<false>(pim, tim, r0, c0, tid, hb, msum, lsum);

    // ---- block reduction of (msum, lsum)
    #pragma unroll
    for (int o = 16; o; o >>= 1) {
        msum += __shfl_down_sync(0xffffffffu, msum, o);
        lsum += __shfl_down_sync(0xffffffffu, lsum, o);
    }
    int lane = tid & 31, wid = tid >> 5;
    if (!lane) { ws[wid] = msum; ws[8 + wid] = lsum; }
    __syncthreads();
    if (wid == 0) {
        msum = (lane < 8) ? ws[lane] : 0.0f;
        lsum = (lane < 8) ? ws[8 + lane] : 0.0f;
        #pragma unroll
        for (int o = 4; o; o >>= 1) {
            msum += __shfl_down_sync(0xffffffffu, msum, o);
            lsum += __shfl_down_sync(0xffffffffu, lsum, o);
        }
        if (!lane) {
            atomicAdd(&g_accum[0], (double)msum);
            atomicAdd(&g_accum[1], (double)lsum);
            __threadfence();
            unsigned done = atomicAdd(&g_count, 1u);
            if (done == NBLOCKS - 1) {
                // all blocks' fenced atomics visible; read via atomic RMW
                double a0 = atomicAdd(&g_accum[0], 0.0);
                double a1 = atomicAdd(&g_accum[1], 0.0);
                double mse = a0 / (double)(B * H * W);
                double smean = a1 / ((double)B * OV * OV);
                out[0] = (float)(0.6 * mse + 0.4 * (1.0 - smean));
                // reset for next graph replay (replays are serialized)
                g_accum[0] = 0.0;
                g_accum[1] = 0.0;
                g_count = 0u;
            }
        }
    }
}

// ---------------------------------------------------------------------------
extern "C" void kernel_launch(void* const* d_in, const int* in_sizes, int n_in,
                              void* d_out, int out_size)
{
    const float* pred = (const float*)d_in[0];
    const float* targ = (const float*)d_in[1];

    cudaFuncSetAttribute(fused_kernel,
                         cudaFuncAttributeMaxDynamicSharedMemorySize, SMEM_SZ);

    dim3 grid(16, NTROW, B);   // 16 col-tiles x 11 row-tiles x 32 images
    fused_kernel<<<grid, 256, SMEM_SZ>>>(pred, targ, (float*)d_out);
}

// round 15
// speedup vs baseline: 1.2198x; 1.0786x over previous
#include <cuda_runtime.h>

// ---------------------------------------------------------------------------
// Fully fused MSE + SSIM loss, 32x1x512x512 fp32 -> scalar. ONE kernel.
// Round-15: perfect-fit tile. TOR=54 -> TIR=64 -> hconv is EXACTLY 512
// tasks = 2 full 256-thread passes (100% lane util, was 90.6%). vconv:
// 8 warps x 7 rows (rows 54/55 masked; hb sized 66 rows so their garbage
// window reads stay in-bounds). Single code version (no INTERIOR dup).
// Dataflow = round-8: gmem-direct hconv (coalesced float4), permuted
// conflict-free STS (storage col = cg + 8j), packed fma.rn.f32x2 chains,
// fused MSE, __fdividef epilogue, per-block reduce + last-block epilogue.
// ---------------------------------------------------------------------------

#define H 512
#define W 512
#define B 32
#define OV 502            // valid output size (512 - 11 + 1)
#define TOR 54            // output tile rows
#define TOC 32            // output tile cols
#define TIR 64            // input tile rows (TOR + 10) -> 64*8 = 512 tasks
#define HBROWS 66         // hb rows (vconv warp 7 window reach: 49+16=65)
#define HBS 33            // hb row stride in ulonglong2 (528B: coeff 4 mod 32)
#define NTROW 10          // row tiles (10*54 = 540 >= 502)
#define NBLOCKS (16 * NTROW * 32)   // 5120

#define HB_BYTES  (HBROWS * HBS * 16)    // 34848
#define SMEM_SZ   (HB_BYTES + 64)        // 34912 -> 5 CTAs/SM (reg-limited)

typedef unsigned long long u64;

__device__ __forceinline__ u64 pk2(float lo, float hi) {
    u64 r; asm("mov.b64 %0, {%1, %2};" : "=l"(r) : "f"(lo), "f"(hi)); return r;
}
__device__ __forceinline__ void upk2(u64 v, float& lo, float& hi) {
    asm("mov.b64 {%0, %1}, %2;" : "=f"(lo), "=f"(hi) : "l"(v));
}
__device__ __forceinline__ u64 ffma2(u64 a, u64 w, u64 c) {
    u64 d; asm("fma.rn.f32x2 %0, %1, %2, %3;" : "=l"(d) : "l"(a), "l"(w), "l"(c));
    return d;
}

// 11-tap Gaussian, sigma=1.5, normalized; symmetric -> 6 distinct values.
#define GW0 0.00102838f
#define GW1 0.00759875f
#define GW2 0.03600077f
#define GW3 0.10936080f
#define GW4 0.21300549f
#define GW5 0.26601166f
#define DECLARE_W2                                                            \
    const u64 W2[11] = {                                                      \
        pk2(GW0, GW0), pk2(GW1, GW1), pk2(GW2, GW2), pk2(GW3, GW3),           \
        pk2(GW4, GW4), pk2(GW5, GW5),                                         \
        pk2(GW4, GW4), pk2(GW3, GW3), pk2(GW2, GW2), pk2(GW1, GW1),           \
        pk2(GW0, GW0) };

__device__ double g_accum[2] = {0.0, 0.0};   // [0]=mse sum, [1]=ssim sum
__device__ unsigned int g_count = 0;

__global__ __launch_bounds__(256, 5) void fused_kernel(
    const float* __restrict__ pred, const float* __restrict__ targ,
    float* __restrict__ out)
{
    extern __shared__ __align__(16) char dsm[];
    ulonglong2 (*hb)[HBS] = (ulonglong2(*)[HBS])dsm;   // (A,B) packed pairs
    float* ws = (float*)(dsm + HB_BYTES);

    const int tid = threadIdx.x;
    const int r0 = blockIdx.y * TOR;
    const int c0 = blockIdx.x * TOC;
    const float* pim = pred + (size_t)blockIdx.z * (H * W);
    const float* tim = targ + (size_t)blockIdx.z * (H * W);

    float msum = 0.0f, lsum = 0.0f;

    // ---- fused gmem-load + horizontal conv. 64 rows x 8 col-groups =
    // exactly 512 tasks = 2 full passes of 256 threads (zero idle lanes).
    // Warp lanes = (cg, row) -> coalesced LDG; permuted conflict-free STS.
    {
        DECLARE_W2
        #pragma unroll
        for (int pass = 0; pass < 2; pass++) {
            const int t = tid + 256 * pass;
            const int row = t >> 3, cg = t & 7;
            const int gr = min(r0 + row, H - 1);
            const float* prow = pim + gr * W;
            const float* trow = tim + gr * W;
            const int cbase = c0 + 4 * cg;

            float4 P[4], T[4];
            #pragma unroll
            for (int j = 0; j < 4; j++) {
                int gc = min(cbase + 4 * j, W - 4);   // clamp dups feed only
                P[j] = *(const float4*)(prow + gc);   // masked outputs
                T[j] = *(const float4*)(trow + gc);
            }

            // MSE: task owns pixels (gr, cbase..cbase+3) exactly once
            // (clamped bottom rows excluded via r0+row < H).
            if (row < TOR && (r0 + row) < H) {
                float d0 = P[0].x - T[0].x, d1 = P[0].y - T[0].y;
                float d2 = P[0].z - T[0].z, d3 = P[0].w - T[0].w;
                msum = fmaf(d0, d0, msum); msum = fmaf(d1, d1, msum);
                msum = fmaf(d2, d2, msum); msum = fmaf(d3, d3, msum);
            }

            u64 win[14];
            #pragma unroll
            for (int j = 0; j < 4; j++) {
                if (4 * j + 0 < 14) win[4 * j + 0] = pk2(P[j].x, T[j].x);
                if (4 * j + 1 < 14) win[4 * j + 1] = pk2(P[j].y, T[j].y);
                if (4 * j + 2 < 14) win[4 * j + 2] = pk2(P[j].z, T[j].z);
                if (4 * j + 3 < 14) win[4 * j + 3] = pk2(P[j].w, T[j].w);
            }

            u64 a0 = 0, a1 = 0, a2 = 0, a3 = 0;
            #pragma unroll
            for (int k = 0; k < 11; k++) {
                a0 = ffma2(win[k + 0], W2[k], a0);
                a1 = ffma2(win[k + 1], W2[k], a1);
                a2 = ffma2(win[k + 2], W2[k], a2);
                a3 = ffma2(win[k + 3], W2[k], a3);
            }
            #pragma unroll
            for (int k = 0; k < 14; k++) {   // (p,t) -> (p^2+t^2, p*t)
                float p, tt;
                upk2(win[k], p, tt);
                win[k] = pk2(fmaf(p, p, tt * tt), p * tt);
            }
            u64 b0 = 0, b1 = 0, b2 = 0, b3 = 0;
            #pragma unroll
            for (int k = 0; k < 11; k++) {
                b0 = ffma2(win[k + 0], W2[k], b0);
                b1 = ffma2(win[k + 1], W2[k], b1);
                b2 = ffma2(win[k + 2], W2[k], b2);
                b3 = ffma2(win[k + 3], W2[k], b3);
            }
            // permuted store: storage col = cg + 8j holds actual col 4cg+j.
            // Quarter-warp (8 lanes, same row, cg 0..7) writes 128B
            // contiguous -> 4-wavefront STS.128.
            hb[row][cg +  0] = make_ulonglong2(a0, b0);
            hb[row][cg +  8] = make_ulonglong2(a1, b1);
            hb[row][cg + 16] = make_ulonglong2(a2, b2);
            hb[row][cg + 24] = make_ulonglong2(a3, b3);
        }
    }
    __syncthreads();

    // ---- vertical 11-tap conv, streaming: each thread owns (storage col,
    // 7 rows). 17 LDS.128, 28 packed accumulators, then SSIM epilogue.
    // Warp 7's rows 54/55 are masked (their hb window rows 64/65 are
    // unwritten garbage read in-bounds and discarded).
    {
        DECLARE_W2
        const int c = tid & 31;                    // storage column
        const int acol = 4 * (c & 7) + (c >> 3);   // actual column
        const int rb = (tid >> 5) * 7;             // 0,7,...,49

        u64 accA[7], accB[7];
        #pragma unroll
        for (int j = 0; j < 7; j++) { accA[j] = 0; accB[j] = 0; }

        #pragma unroll
        for (int k = 0; k < 17; k++) {
            ulonglong2 v = hb[rb + k][c];
            #pragma unroll
            for (int j = 0; j < 7; j++) {
                if (k - j >= 0 && k - j <= 10) {
                    accA[j] = ffma2(v.x, W2[k - j], accA[j]);
                    accB[j] = ffma2(v.y, W2[k - j], accB[j]);
                }
            }
        }

        const float C1 = 1e-4f, C2 = 9e-4f;
        const int ocol = c0 + acol;
        #pragma unroll
        for (int j = 0; j < 7; j++) {
            int orow = r0 + rb + j;
            if ((rb + j) < TOR && orow < OV && ocol < OV) {
                float m1, m2, bsv, bptv;
                upk2(accA[j], m1, m2);
                upk2(accB[j], bsv, bptv);
                float m1s = m1 * m1, m2s = m2 * m2, m12 = m1 * m2;
                float musum = m1s + m2s;
                float sigsum = bsv - musum;           // sigma1^2 + sigma2^2
                float s12 = bptv - m12;               // sigma12
                float num = (2.0f * m12 + C1) * (2.0f * s12 + C2);
                float den = (musum + C1) * (sigsum + C2) + 1e-6f;
                lsum += __fdividef(num, den);
            }
        }
    }

    // ---- block reduction of (msum, lsum)
    #pragma unroll
    for (int o = 16; o; o >>= 1) {
        msum += __shfl_down_sync(0xffffffffu, msum, o);
        lsum += __shfl_down_sync(0xffffffffu, lsum, o);
    }
    int lane = tid & 31, wid = tid >> 5;
    if (!lane) { ws[wid] = msum; ws[8 + wid] = lsum; }
    __syncthreads();
    if (wid == 0) {
        msum = (lane < 8) ? ws[lane] : 0.0f;
        lsum = (lane < 8) ? ws[8 + lane] : 0.0f;
        #pragma unroll
        for (int o = 4; o; o >>= 1) {
            msum += __shfl_down_sync(0xffffffffu, msum, o);
            lsum += __shfl_down_sync(0xffffffffu, lsum, o);
        }
        if (!lane) {
            atomicAdd(&g_accum[0], (double)msum);
            atomicAdd(&g_accum[1], (double)lsum);
            __threadfence();
            unsigned done = atomicAdd(&g_count, 1u);
            if (done == NBLOCKS - 1) {
                // all blocks' fenced atomics visible; read via atomic RMW
                double a0 = atomicAdd(&g_accum[0], 0.0);
                double a1 = atomicAdd(&g_accum[1], 0.0);
                double mse = a0 / (double)(B * H * W);
                double smean = a1 / ((double)B * OV * OV);
                out[0] = (float)(0.6 * mse + 0.4 * (1.0 - smean));
                // reset for next graph replay (replays are serialized)
                g_accum[0] = 0.0;
                g_accum[1] = 0.0;
                g_count = 0u;
            }
        }
    }
}

// ---------------------------------------------------------------------------
extern "C" void kernel_launch(void* const* d_in, const int* in_sizes, int n_in,
                              void* d_out, int out_size)
{
    const float* pred = (const float*)d_in[0];
    const float* targ = (const float*)d_in[1];

    cudaFuncSetAttribute(fused_kernel,
                         cudaFuncAttributeMaxDynamicSharedMemorySize, SMEM_SZ);

    dim3 grid(16, NTROW, B);   // 16 col-tiles x 10 row-tiles x 32 images
    fused_kernel<<<grid, 256, SMEM_SZ>>>(pred, targ, (float*)d_out);
}